// round 15
// baseline (speedup 1.0000x reference)
#include <cuda_runtime.h>
#include <cuda_bf16.h>
#include <math.h>
#include <stdint.h>

#define Bb 2
#define Ss 2048
#define Hh 1024
#define NHEAD 16
#define HDIM 64
#define MTOT (Bb*Ss)

__device__ int g_idx[Bb][Ss];
__device__ int g_nv[Bb];
// Permuted fragment-unit operands (16B unit = [hi_k0k1|hi_k8k9|lo_k0k1|lo_k8k9])
__device__ uint4 g_Xp[(size_t)3 * MTOT * 256];   // inputs q,k,v (k/v rows compacted)
__device__ uint4 g_Wp[(size_t)3 * Hh * 256];     // weights
// Q bf16 split (plain layout, attn A operand)
__device__ __nv_bfloat16 g_Qbh[MTOT * Hh];
__device__ __nv_bfloat16 g_Qbl[MTOT * Hh];
// K permuted fragment layout (per token, per head, 16 units)
__device__ uint32_t g_Kp[MTOT * 1024];
// V transposed+permuted (per (bh*64+d) row, per 64-kv tile, 16 units)
__device__ uint32_t g_Vp[(size_t)Bb * NHEAD * HDIM * Ss];

__device__ __forceinline__ uint32_t smem_u32(const void* p) {
    uint32_t a;
    asm("{ .reg .u64 t; cvta.to.shared.u64 t, %1; cvt.u32.u64 %0, t; }" : "=r"(a) : "l"(p));
    return a;
}

#define CP_ASYNC16(saddr, gptr) \
    asm volatile("cp.async.cg.shared.global [%0], [%1], 16;" :: "r"(saddr), "l"(gptr) : "memory")
#define CP_COMMIT() asm volatile("cp.async.commit_group;" ::: "memory")
#define CP_WAIT1()  asm volatile("cp.async.wait_group 1;" ::: "memory")
#define CP_WAIT0()  asm volatile("cp.async.wait_group 0;" ::: "memory")

__device__ __forceinline__ void mma16816b(float d[4], const uint32_t a[4],
                                          uint32_t b0, uint32_t b1) {
    asm volatile(
        "mma.sync.aligned.m16n8k16.row.col.f32.bf16.bf16.f32 "
        "{%0,%1,%2,%3}, {%4,%5,%6,%7}, {%8,%9}, {%0,%1,%2,%3};"
        : "+f"(d[0]), "+f"(d[1]), "+f"(d[2]), "+f"(d[3])
        : "r"(a[0]), "r"(a[1]), "r"(a[2]), "r"(a[3]), "r"(b0), "r"(b1));
}

__device__ __forceinline__ uint32_t packbf(float lo, float hi) {
    uint32_t r;
    asm("cvt.rn.bf16x2.f32 %0, %1, %2;" : "=r"(r) : "f"(hi), "f"(lo));
    return r;
}
__device__ __forceinline__ float residbf(float p) {
    return p - __bfloat162float(__float2bfloat16_rn(p));
}
__device__ __forceinline__ uint32_t prmt7632(float a, float b) {
    uint32_t r;
    asm("prmt.b32 %0, %1, %2, 0x7632;"
        : "=r"(r) : "r"(__float_as_uint(a)), "r"(__float_as_uint(b)));
    return r;
}
__device__ __forceinline__ float truncbf(float x) {
    return __uint_as_float(__float_as_uint(x) & 0xFFFF0000u);
}

// ---------------------------------------------------------------------------
// Valid-key compaction
// ---------------------------------------------------------------------------
__global__ __launch_bounds__(1024) void compact_kernel(const int* __restrict__ mask)
{
    __shared__ int s0[1024], s1[1024];
    const int b = blockIdx.x;
    const int t = threadIdx.x;
    const int m0 = mask[b * Ss + 2 * t] != 0;
    const int m1 = mask[b * Ss + 2 * t + 1] != 0;
    s0[t] = m0 + m1;
    __syncthreads();
    int* src = s0; int* dst = s1;
#pragma unroll
    for (int off = 1; off < 1024; off <<= 1) {
        int val = src[t];
        if (t >= off) val += src[t - off];
        dst[t] = val;
        __syncthreads();
        int* tmp = src; src = dst; dst = tmp;
    }
    const int excl = (t == 0) ? 0 : src[t - 1];
    if (m0) g_idx[b][excl] = 2 * t;
    if (m1) g_idx[b][excl + m0] = 2 * t + 1;
    if (t == 1023) g_nv[b] = src[1023];
}

// ---------------------------------------------------------------------------
// Split fp32 -> permuted fragment units (hi/lo interleaved per 16B unit).
// z 0..2: inputs (k/v rows compacted); z 3..5: weights.
// unit(row, grp, tg) covers k = grp*16 + tg*2 (+1) and +8 (+9).
// ---------------------------------------------------------------------------
__global__ __launch_bounds__(256) void split_kernel(
    const float* __restrict__ xq, const float* __restrict__ xk, const float* __restrict__ xv,
    const float* __restrict__ Wq, const float* __restrict__ Wk, const float* __restrict__ Wv)
{
    const int z = blockIdx.y;
    const float* srcm;
    uint4* dstm;
    int nrows;
    if (z < 3) {
        srcm = (z == 0) ? xq : (z == 1) ? xk : xv;
        dstm = g_Xp + (size_t)z * MTOT * 256;
        nrows = MTOT;
    } else {
        const int w = z - 3;
        srcm = (w == 0) ? Wq : (w == 1) ? Wk : Wv;
        dstm = g_Wp + (size_t)w * Hh * 256;
        nrows = Hh;
    }
    const int i = blockIdx.x * 256 + threadIdx.x;
    if (i >= nrows * 256) return;
    const int row = i >> 8;
    const int u = i & 255;
    const int grp = u >> 2, tg = u & 3;
    const int k0 = grp * 16 + tg * 2;

    size_t srow = (size_t)row;
    if (z == 1 || z == 2) {
        const int b = row >> 11, rr = row & 2047;
        if (rr >= g_nv[b]) return;
        srow = (size_t)(b * Ss + g_idx[b][rr]);
    }
    const float2 v01 = *(const float2*)&srcm[srow * Hh + k0];
    const float2 v89 = *(const float2*)&srcm[srow * Hh + k0 + 8];
    uint4 unit;
    unit.x = packbf(v01.x, v01.y);
    unit.y = packbf(v89.x, v89.y);
    unit.z = packbf(residbf(v01.x), residbf(v01.y));
    unit.w = packbf(residbf(v89.x), residbf(v89.y));
    dstm[(size_t)row * 256 + u] = unit;
}

// ---------------------------------------------------------------------------
// proj GEMM — 128x256 tile, 1 CTA/SM, permuted-fragment smem (LDS.128 loads).
// Per 64-K chunk: load A/B units once, run 3 passes (hh, lh, hl).
// Epilogues: z=0 Q plain bf16 h/l, z=1 K permuted, z=2 V transposed+permuted.
// ---------------------------------------------------------------------------
#define ABLK 2080                        // 128*16 + 32 (tig*2080 % 128 == tig*32)
#define BBLK 4128                        // 256*16 + 32
#define A_REG (16 * ABLK)                // 33280
#define BUF2 (A_REG + 16 * BBLK)         // 99328
#define PSMEM (2 * BUF2)                 // 198656
#define NCHUNK 16
#define TSTR 132

__global__ __launch_bounds__(256, 1) void proj_mma_kernel(
    const float* __restrict__ bq, const float* __restrict__ bk, const float* __restrict__ bv)
{
    const int z = blockIdx.z;
    const int bm = blockIdx.y * 128;
    if (z != 0) {
        const int bat = bm >> 11;
        if ((bm & 2047) >= g_nv[bat]) return;
    }
    extern __shared__ char smem[];
    const uint32_t sbase = smem_u32(smem);
    const int tid = threadIdx.x;
    const uint4* Xp = g_Xp + (size_t)z * MTOT * 256;
    const uint4* Wp = g_Wp + (size_t)z * Hh * 256;
    const float* bias = (z == 0) ? bq : (z == 1) ? bk : bv;
    const int bn = blockIdx.x * 256;

    const int wid = tid >> 5, lane = tid & 31;
    const int wm = wid & 1;
    const int wn = wid >> 1;
    const int g = lane >> 2;
    const int tig = lane & 3;

    float d[4][8][4];
#pragma unroll
    for (int mt = 0; mt < 4; mt++)
#pragma unroll
        for (int nt = 0; nt < 8; nt++)
#pragma unroll
            for (int r = 0; r < 4; r++) d[mt][nt][r] = 0.f;

    auto issue_chunk = [&](int c, int buf) {
        const uint32_t base = sbase + buf * BUF2;
        // A: 128 rows x 16 units
#pragma unroll
        for (int i = 0; i < 8; i++) {
            int idx = i * 256 + tid;
            int row = idx >> 4;
            int u = idx & 15;
            CP_ASYNC16(base + u * ABLK + row * 16,
                       Xp + (size_t)(bm + row) * 256 + c * 16 + u);
        }
        // B: 256 rows x 16 units
#pragma unroll
        for (int i = 0; i < 16; i++) {
            int idx = i * 256 + tid;
            int row = idx >> 4;
            int u = idx & 15;
            CP_ASYNC16(base + A_REG + u * BBLK + row * 16,
                       Wp + (size_t)(bn + row) * 256 + c * 16 + u);
        }
        CP_COMMIT();
    };

    issue_chunk(0, 0);

    for (int c = 0; c < NCHUNK; c++) {
        const int buf = c & 1;
        if (c + 1 < NCHUNK) {
            issue_chunk(c + 1, buf ^ 1);
            CP_WAIT1();
        } else {
            CP_WAIT0();
        }
        __syncthreads();

        const char* Ab = smem + buf * BUF2;
        const char* Bbp = Ab + A_REG;
#pragma unroll
        for (int ks = 0; ks < 4; ks++) {
            // A fragments: 2 LDS.128 per mt (rows g and g+8)
            uint32_t afh[4][4], afl[4][4];
#pragma unroll
            for (int mt = 0; mt < 4; mt++) {
                const char* p = Ab + (ks * 4 + tig) * ABLK + (wm * 64 + mt * 16 + g) * 16;
                uint4 a0 = *(const uint4*)(p);
                uint4 a1 = *(const uint4*)(p + 128);
                afh[mt][0] = a0.x; afh[mt][1] = a1.x; afh[mt][2] = a0.y; afh[mt][3] = a1.y;
                afl[mt][0] = a0.z; afl[mt][1] = a1.z; afl[mt][2] = a0.w; afl[mt][3] = a1.w;
            }
            // B fragments: 1 LDS.128 per nt
            uint4 bu[8];
#pragma unroll
            for (int nt = 0; nt < 8; nt++)
                bu[nt] = *(const uint4*)(Bbp + (ks * 4 + tig) * BBLK + (wn * 64 + nt * 8 + g) * 16);
            // pass 1: hh
#pragma unroll
            for (int mt = 0; mt < 4; mt++)
#pragma unroll
                for (int nt = 0; nt < 8; nt++)
                    mma16816b(d[mt][nt], afh[mt], bu[nt].x, bu[nt].y);
            // pass 2: lh
#pragma unroll
            for (int mt = 0; mt < 4; mt++)
#pragma unroll
                for (int nt = 0; nt < 8; nt++)
                    mma16816b(d[mt][nt], afl[mt], bu[nt].x, bu[nt].y);
            // pass 3: hl
#pragma unroll
            for (int mt = 0; mt < 4; mt++)
#pragma unroll
                for (int nt = 0; nt < 8; nt++)
                    mma16816b(d[mt][nt], afh[mt], bu[nt].z, bu[nt].w);
        }
        __syncthreads();
    }

    if (z == 0) {
        // Q epilogue: plain bf16 hi/lo
#pragma unroll
        for (int nt = 0; nt < 8; nt++) {
            const int col = bn + wn * 64 + nt * 8 + 2 * tig;
            const float2 bb = *(const float2*)&bias[col];
#pragma unroll
            for (int mt = 0; mt < 4; mt++) {
                const int row = bm + wm * 64 + mt * 16 + g;
                float y0 = d[mt][nt][0] + bb.x;
                float y1 = d[mt][nt][1] + bb.y;
                float y2 = d[mt][nt][2] + bb.x;
                float y3 = d[mt][nt][3] + bb.y;
                const size_t o0 = ((size_t)row * Hh + col) >> 1;
                const size_t o1 = ((size_t)(row + 8) * Hh + col) >> 1;
                ((uint32_t*)g_Qbh)[o0] = packbf(y0, y1);
                ((uint32_t*)g_Qbh)[o1] = packbf(y2, y3);
                ((uint32_t*)g_Qbl)[o0] = packbf(residbf(y0), residbf(y1));
                ((uint32_t*)g_Qbl)[o1] = packbf(residbf(y2), residbf(y3));
            }
        }
    } else if (z == 1) {
        // K epilogue: permuted fragment units
#pragma unroll
        for (int nt = 0; nt < 8; nt++) {
            const int col = bn + wn * 64 + nt * 8 + 2 * tig;
            const float2 bb = *(const float2*)&bias[col];
            const int head = col >> 6;
            const int dd = col & 63;
            const int kc = dd >> 4;
            const int j = dd & 15;
            const int whi = (j >= 8) ? 1 : 0;
            const int tigk = (j & 7) >> 1;
            const int wunit = head * 64 + (kc * 4 + tigk) * 4 + whi;
#pragma unroll
            for (int mt = 0; mt < 4; mt++) {
                const int row = bm + wm * 64 + mt * 16 + g;
                float y0 = d[mt][nt][0] + bb.x;
                float y1 = d[mt][nt][1] + bb.y;
                float y2 = d[mt][nt][2] + bb.x;
                float y3 = d[mt][nt][3] + bb.y;
                const size_t w0 = (size_t)row * 1024 + wunit;
                const size_t w1 = (size_t)(row + 8) * 1024 + wunit;
                g_Kp[w0] = packbf(y0, y1);
                g_Kp[w0 + 2] = packbf(residbf(y0), residbf(y1));
                g_Kp[w1] = packbf(y2, y3);
                g_Kp[w1 + 2] = packbf(residbf(y2), residbf(y3));
            }
        }
    } else {
        // V epilogue: transpose in smem then write permuted units
        float* smt = (float*)smem;
#pragma unroll
        for (int nt = 0; nt < 8; nt++) {
            const int col = wn * 64 + nt * 8 + 2 * tig;
            const float2 bb = *(const float2*)&bias[bn + col];
#pragma unroll
            for (int mt = 0; mt < 4; mt++) {
                const int row = wm * 64 + mt * 16 + g;
                smt[col * TSTR + row]           = d[mt][nt][0] + bb.x;
                smt[(col + 1) * TSTR + row]     = d[mt][nt][1] + bb.y;
                smt[col * TSTR + row + 8]       = d[mt][nt][2] + bb.x;
                smt[(col + 1) * TSTR + row + 8] = d[mt][nt][3] + bb.y;
            }
        }
        __syncthreads();
        const int b = bm >> 11;
        const int kvb = bm & 2047;
#pragma unroll
        for (int it = 0; it < 16; it++) {
            const int idx = it * 256 + tid;
            const int col = idx >> 4;
            const int seg = idx & 15;
            const int dcol = bn + col;
            const int head = dcol >> 6;
            const int dd = dcol & 63;
            const int bh = b * NHEAD + head;
            const int t = ((kvb + seg * 8) >> 6);
            const int s = seg & 7;
            const int kc = s >> 1;
            const int wb = s & 1;
            const size_t base =
                ((size_t)(bh * HDIM + dd) * (Ss >> 6) + t) * 64 + kc * 16 + wb;
            float v[8];
#pragma unroll
            for (int j = 0; j < 8; j++) v[j] = smt[col * TSTR + seg * 8 + j];
#pragma unroll
            for (int p = 0; p < 4; p++) {
                g_Vp[base + p * 4]     = packbf(v[2*p], v[2*p+1]);
                g_Vp[base + p * 4 + 2] = packbf(residbf(v[2*p]), residbf(v[2*p+1]));
            }
        }
    }
}

// ---------------------------------------------------------------------------
// Tensorized flash attention — unchanged from R14 (permuted K/V, LDS.128).
// ---------------------------------------------------------------------------
#define AROW 144
#define QROWS 64
#define Q_BYTES (QROWS * AROW)
#define KVROW 320
#define KBYTES (64 * KVROW)
#define TILE2 (2 * KBYTES)
#define SM_KV0 (2 * Q_BYTES)
#define ATT2_SMEM (SM_KV0 + 2 * TILE2)

__global__ __launch_bounds__(128, 2) void attn_mma_kernel(float* __restrict__ out)
{
    extern __shared__ char smem[];
    const uint32_t sbase = smem_u32(smem);
    const int tid = threadIdx.x;
    const int q0 = blockIdx.x * QROWS;
    const int h = blockIdx.y;
    const int b = blockIdx.z;
    const int bh = b * NHEAD + h;
    const int nvb = g_nv[b];
    const int ntile = (nvb + 63) >> 6;

    const int wid = tid >> 5, lane = tid & 31;
    const int wq = wid * 16;
    const int g = lane >> 2;
    const int tig = lane & 3;

    {
#pragma unroll
        for (int i = 0; i < 8; i++) {
            int idx = i * 128 + tid;
            int arr = idx >> 9;
            int r = (idx >> 3) & 63;
            int seg = idx & 7;
            const __nv_bfloat16* src =
                (arr ? g_Qbl : g_Qbh) + (size_t)(b * Ss + q0 + r) * Hh + h * HDIM + seg * 8;
            CP_ASYNC16(sbase + arr * Q_BYTES + r * AROW + seg * 16, src);
        }
    }
    auto issue_tile = [&](int t, int buf) {
        const int kv0 = t * 64;
        const uint32_t tb = sbase + SM_KV0 + buf * TILE2;
#pragma unroll
        for (int i = 0; i < 16; i++) {
            int idx = i * 128 + tid;
            int arr = idx >> 10;
            int r = (idx >> 4) & 63;
            int u = idx & 15;
            const uint32_t* src;
            if (arr == 0)
                src = g_Kp + (size_t)(b * Ss + kv0 + r) * 1024 + h * 64 + u * 4;
            else
                src = g_Vp + ((size_t)(bh * HDIM + r) * (Ss >> 6) + t) * 64 + u * 4;
            CP_ASYNC16(tb + arr * KBYTES + r * KVROW + u * 16, src);
        }
    };

    issue_tile(0, 0);
    CP_COMMIT();

    uint32_t aQh[4][4], aQl[4][4];
    float o[8][4];
    float rs0 = 0.f, rs1 = 0.f;
#pragma unroll
    for (int nd = 0; nd < 8; nd++)
#pragma unroll
        for (int r = 0; r < 4; r++) o[nd][r] = 0.f;

    for (int t = 0; t < ntile; t++) {
        const int buf = t & 1;
        if (t + 1 < ntile) {
            issue_tile(t + 1, buf ^ 1);
            CP_COMMIT();
            CP_WAIT1();
        } else {
            CP_WAIT0();
        }
        __syncthreads();

        if (t == 0) {
#pragma unroll
            for (int kc = 0; kc < 4; kc++) {
                const char* p = smem + (wq + g) * AROW + kc * 32 + tig * 4;
                aQh[kc][0] = *(const uint32_t*)(p);
                aQh[kc][1] = *(const uint32_t*)(p + 8 * AROW);
                aQh[kc][2] = *(const uint32_t*)(p + 16);
                aQh[kc][3] = *(const uint32_t*)(p + 8 * AROW + 16);
                const char* q = p + Q_BYTES;
                aQl[kc][0] = *(const uint32_t*)(q);
                aQl[kc][1] = *(const uint32_t*)(q + 8 * AROW);
                aQl[kc][2] = *(const uint32_t*)(q + 16);
                aQl[kc][3] = *(const uint32_t*)(q + 8 * AROW + 16);
            }
        }

        const char* KB = smem + SM_KV0 + buf * TILE2;
        const char* VB = KB + KBYTES;

        float s[8][4];
#pragma unroll
        for (int nt = 0; nt < 8; nt++)
#pragma unroll
            for (int r = 0; r < 4; r++) s[nt][r] = 0.f;

#pragma unroll
        for (int kc = 0; kc < 4; kc++) {
            uint4 kk[8];
#pragma unroll
            for (int nt = 0; nt < 8; nt++)
                kk[nt] = *(const uint4*)(KB + (nt * 8 + g) * KVROW + kc * 64 + tig * 16);
#pragma unroll
            for (int nt = 0; nt < 8; nt++) mma16816b(s[nt], aQh[kc], kk[nt].x, kk[nt].y);
#pragma unroll
            for (int nt = 0; nt < 8; nt++) mma16816b(s[nt], aQl[kc], kk[nt].x, kk[nt].y);
#pragma unroll
            for (int nt = 0; nt < 8; nt++) mma16816b(s[nt], aQh[kc], kk[nt].z, kk[nt].w);
        }

        const int kvb = t * 64 + 2 * tig;
#pragma unroll
        for (int nt = 0; nt < 8; nt++) {
            const int c0 = kvb + nt * 8;
            float p0 = (c0 < nvb) ? __expf(s[nt][0]) : 0.f;
            float p1 = (c0 + 1 < nvb) ? __expf(s[nt][1]) : 0.f;
            float p2 = (c0 < nvb) ? __expf(s[nt][2]) : 0.f;
            float p3 = (c0 + 1 < nvb) ? __expf(s[nt][3]) : 0.f;
            rs0 += p0 + p1;
            rs1 += p2 + p3;
            s[nt][0] = p0; s[nt][1] = p1; s[nt][2] = p2; s[nt][3] = p3;
        }

        uint32_t pah[4][4], pal[4][4];
#pragma unroll
        for (int kc = 0; kc < 4; kc++) {
            const int n0 = 2 * kc, n1 = 2 * kc + 1;
            pah[kc][0] = prmt7632(s[n0][0], s[n0][1]);
            pah[kc][1] = prmt7632(s[n0][2], s[n0][3]);
            pah[kc][2] = prmt7632(s[n1][0], s[n1][1]);
            pah[kc][3] = prmt7632(s[n1][2], s[n1][3]);
            pal[kc][0] = packbf(s[n0][0] - truncbf(s[n0][0]), s[n0][1] - truncbf(s[n0][1]));
            pal[kc][1] = packbf(s[n0][2] - truncbf(s[n0][2]), s[n0][3] - truncbf(s[n0][3]));
            pal[kc][2] = packbf(s[n1][0] - truncbf(s[n1][0]), s[n1][1] - truncbf(s[n1][1]));
            pal[kc][3] = packbf(s[n1][2] - truncbf(s[n1][2]), s[n1][3] - truncbf(s[n1][3]));
        }

#pragma unroll
        for (int kc = 0; kc < 4; kc++) {
            uint4 vv[8];
#pragma unroll
            for (int nd = 0; nd < 8; nd++)
                vv[nd] = *(const uint4*)(VB + (nd * 8 + g) * KVROW + kc * 64 + tig * 16);
#pragma unroll
            for (int nd = 0; nd < 8; nd++) mma16816b(o[nd], pah[kc], vv[nd].x, vv[nd].y);
#pragma unroll
            for (int nd = 0; nd < 8; nd++) mma16816b(o[nd], pal[kc], vv[nd].x, vv[nd].y);
#pragma unroll
            for (int nd = 0; nd < 8; nd++) mma16816b(o[nd], pah[kc], vv[nd].z, vv[nd].w);
        }
        __syncthreads();
    }

    rs0 += __shfl_xor_sync(0xffffffffu, rs0, 1);
    rs0 += __shfl_xor_sync(0xffffffffu, rs0, 2);
    rs1 += __shfl_xor_sync(0xffffffffu, rs1, 1);
    rs1 += __shfl_xor_sync(0xffffffffu, rs1, 2);
    const float inv0 = 1.f / rs0;
    const float inv1 = 1.f / rs1;
    const int qg = q0 + wq + g;
    float* op0 = out + (size_t)(b * Ss + qg) * Hh + h * HDIM;
    float* op1 = out + (size_t)(b * Ss + qg + 8) * Hh + h * HDIM;
#pragma unroll
    for (int nd = 0; nd < 8; nd++) {
        const int col = nd * 8 + 2 * tig;
        float2 v0 = {o[nd][0] * inv0, o[nd][1] * inv0};
        float2 v1 = {o[nd][2] * inv1, o[nd][3] * inv1};
        *(float2*)&op0[col] = v0;
        *(float2*)&op1[col] = v1;
    }
}

// ---------------------------------------------------------------------------
extern "C" void kernel_launch(void* const* d_in, const int* in_sizes, int n_in,
                              void* d_out, int out_size)
{
    const float* query = (const float*)d_in[0];
    const float* key   = (const float*)d_in[1];
    const float* value = (const float*)d_in[2];
    const int*   mask  = (const int*)  d_in[3];
    const float* Wq    = (const float*)d_in[4];
    const float* bq    = (const float*)d_in[5];
    const float* Wk    = (const float*)d_in[6];
    const float* bk    = (const float*)d_in[7];
    const float* Wv    = (const float*)d_in[8];
    const float* bv    = (const float*)d_in[9];
    float* out = (float*)d_out;

    compact_kernel<<<Bb, 1024>>>(mask);

    // X: MTOT*256 units -> 4096 blocks; W rows exit early past Hh*256
    split_kernel<<<dim3(MTOT * 256 / 256, 6), 256>>>(query, key, value, Wq, Wk, Wv);

    cudaFuncSetAttribute(proj_mma_kernel,
                         cudaFuncAttributeMaxDynamicSharedMemorySize, PSMEM);
    proj_mma_kernel<<<dim3(Hh / 256, MTOT / 128, 3), 256, PSMEM>>>(bq, bk, bv);

    cudaFuncSetAttribute(attn_mma_kernel,
                         cudaFuncAttributeMaxDynamicSharedMemorySize, ATT2_SMEM);
    attn_mma_kernel<<<dim3(Ss / QROWS, NHEAD, Bb), 128, ATT2_SMEM>>>(out);
}

// round 16
// speedup vs baseline: 1.2587x; 1.2587x over previous
#include <cuda_runtime.h>
#include <cuda_bf16.h>
#include <math.h>
#include <stdint.h>

#define Bb 2
#define Ss 2048
#define Hh 1024
#define NHEAD 16
#define HDIM 64
#define MTOT (Bb*Ss)
#define LOG2E 1.4426950408889634f

__device__ int g_idx[Bb][Ss];
__device__ int g_nv[Bb];
// bf16 split operands for projections
__device__ __nv_bfloat16 g_Xh[3 * MTOT * Hh];
__device__ __nv_bfloat16 g_Xl[3 * MTOT * Hh];
__device__ __nv_bfloat16 g_Wh[3 * Hh * Hh];
__device__ __nv_bfloat16 g_Wl[3 * Hh * Hh];
// Q bf16 split (A-operand layout, pre-scaled by log2e)
__device__ __nv_bfloat16 g_Qbh[MTOT * Hh];
__device__ __nv_bfloat16 g_Qbl[MTOT * Hh];
// K permuted fragment layout: per token, per head, 16 units of 16B
__device__ uint32_t g_Kp[MTOT * 1024];
// V transposed+permuted: per (bh*64+d) row, per 64-kv tile, 16 units
__device__ uint32_t g_Vp[(size_t)Bb * NHEAD * HDIM * Ss];

__device__ __forceinline__ uint32_t smem_u32(const void* p) {
    uint32_t a;
    asm("{ .reg .u64 t; cvta.to.shared.u64 t, %1; cvt.u32.u64 %0, t; }" : "=r"(a) : "l"(p));
    return a;
}

#define CP_ASYNC16(saddr, gptr) \
    asm volatile("cp.async.cg.shared.global [%0], [%1], 16;" :: "r"(saddr), "l"(gptr) : "memory")
#define CP_COMMIT() asm volatile("cp.async.commit_group;" ::: "memory")
#define CP_WAIT1()  asm volatile("cp.async.wait_group 1;" ::: "memory")
#define CP_WAIT0()  asm volatile("cp.async.wait_group 0;" ::: "memory")

__device__ __forceinline__ void mma16816(float d[4], const uint32_t a[4], const uint32_t b[2]) {
    asm volatile(
        "mma.sync.aligned.m16n8k16.row.col.f32.bf16.bf16.f32 "
        "{%0,%1,%2,%3}, {%4,%5,%6,%7}, {%8,%9}, {%0,%1,%2,%3};"
        : "+f"(d[0]), "+f"(d[1]), "+f"(d[2]), "+f"(d[3])
        : "r"(a[0]), "r"(a[1]), "r"(a[2]), "r"(a[3]), "r"(b[0]), "r"(b[1]));
}
__device__ __forceinline__ void mma16816b(float d[4], const uint32_t a[4],
                                          uint32_t b0, uint32_t b1) {
    asm volatile(
        "mma.sync.aligned.m16n8k16.row.col.f32.bf16.bf16.f32 "
        "{%0,%1,%2,%3}, {%4,%5,%6,%7}, {%8,%9}, {%0,%1,%2,%3};"
        : "+f"(d[0]), "+f"(d[1]), "+f"(d[2]), "+f"(d[3])
        : "r"(a[0]), "r"(a[1]), "r"(a[2]), "r"(a[3]), "r"(b0), "r"(b1));
}

__device__ __forceinline__ uint32_t packbf(float lo, float hi) {
    uint32_t r;
    asm("cvt.rn.bf16x2.f32 %0, %1, %2;" : "=r"(r) : "f"(hi), "f"(lo));
    return r;
}
__device__ __forceinline__ float residbf(float p) {
    return p - __bfloat162float(__float2bfloat16_rn(p));
}
__device__ __forceinline__ uint32_t prmt7632(float a, float b) {
    uint32_t r;
    asm("prmt.b32 %0, %1, %2, 0x7632;"
        : "=r"(r) : "r"(__float_as_uint(a)), "r"(__float_as_uint(b)));
    return r;
}
__device__ __forceinline__ float truncbf(float x) {
    return __uint_as_float(__float_as_uint(x) & 0xFFFF0000u);
}

// ---------------------------------------------------------------------------
// Valid-key compaction
// ---------------------------------------------------------------------------
__global__ __launch_bounds__(1024) void compact_kernel(const int* __restrict__ mask)
{
    __shared__ int s0[1024], s1[1024];
    const int b = blockIdx.x;
    const int t = threadIdx.x;
    const int m0 = mask[b * Ss + 2 * t] != 0;
    const int m1 = mask[b * Ss + 2 * t + 1] != 0;
    s0[t] = m0 + m1;
    __syncthreads();
    int* src = s0; int* dst = s1;
#pragma unroll
    for (int off = 1; off < 1024; off <<= 1) {
        int val = src[t];
        if (t >= off) val += src[t - off];
        dst[t] = val;
        __syncthreads();
        int* tmp = src; src = dst; dst = tmp;
    }
    const int excl = (t == 0) ? 0 : src[t - 1];
    if (m0) g_idx[b][excl] = 2 * t;
    if (m1) g_idx[b][excl + m0] = 2 * t + 1;
    if (t == 1023) g_nv[b] = src[1023];
}

// ---------------------------------------------------------------------------
// Split inputs fp32 -> bf16 hi/lo (K/V rows compacted), weights too
// ---------------------------------------------------------------------------
__global__ __launch_bounds__(256) void split_kernel(
    const float* __restrict__ xq, const float* __restrict__ xk, const float* __restrict__ xv,
    const float* __restrict__ Wq, const float* __restrict__ Wk, const float* __restrict__ Wv)
{
    int z = blockIdx.y;
    const float* src;
    __nv_bfloat16 *dh, *dl;
    int n;
    if (z < 3) {
        src = (z == 0) ? xq : (z == 1) ? xk : xv;
        dh = g_Xh + (size_t)z * MTOT * Hh;
        dl = g_Xl + (size_t)z * MTOT * Hh;
        n = MTOT * Hh;
    } else {
        int w = z - 3;
        src = (w == 0) ? Wq : (w == 1) ? Wk : Wv;
        dh = g_Wh + (size_t)w * Hh * Hh;
        dl = g_Wl + (size_t)w * Hh * Hh;
        n = Hh * Hh;
    }
    int i4 = blockIdx.x * blockDim.x + threadIdx.x;
    if (i4 * 4 >= n) return;

    size_t src_off = (size_t)i4 * 4;
    if (z == 1 || z == 2) {
        int row = i4 >> 8;
        int col = (i4 & 255) * 4;
        int b = row >> 11, rr = row & 2047;
        if (rr >= g_nv[b]) return;
        src_off = (size_t)(b * Ss + g_idx[b][rr]) * Hh + col;
    }
    float4 v = *(const float4*)&src[src_off];
    __nv_bfloat16 h0 = __float2bfloat16_rn(v.x);
    __nv_bfloat16 h1 = __float2bfloat16_rn(v.y);
    __nv_bfloat16 h2 = __float2bfloat16_rn(v.z);
    __nv_bfloat16 h3 = __float2bfloat16_rn(v.w);
    __nv_bfloat162 H0 = {h0, h1}, H1 = {h2, h3};
    __nv_bfloat16 l0 = __float2bfloat16_rn(v.x - __bfloat162float(h0));
    __nv_bfloat16 l1 = __float2bfloat16_rn(v.y - __bfloat162float(h1));
    __nv_bfloat16 l2 = __float2bfloat16_rn(v.z - __bfloat162float(h2));
    __nv_bfloat16 l3 = __float2bfloat16_rn(v.w - __bfloat162float(h3));
    __nv_bfloat162 L0 = {l0, l1}, L1 = {l2, l3};
    *(__nv_bfloat162*)&dh[i4 * 4 + 0] = H0;
    *(__nv_bfloat162*)&dh[i4 * 4 + 2] = H1;
    *(__nv_bfloat162*)&dl[i4 * 4 + 0] = L0;
    *(__nv_bfloat162*)&dl[i4 * 4 + 2] = L1;
}

// ---------------------------------------------------------------------------
// mma.sync bf16 projection GEMM — 128x256 CTA tile, 1 CTA/SM (R14 config).
// Epilogue: z=0 -> Q bf16 h/l scaled by log2e, z=1 -> K permuted units,
//           z=2 -> V transposed+permuted units via smem.
// ---------------------------------------------------------------------------
#define KPAD 72
#define ROWB (KPAD * 2)
#define AH_OFF 0
#define AL_OFF (128 * ROWB)
#define BH_OFF (2 * 128 * ROWB)
#define BL_OFF (BH_OFF + 256 * ROWB)
#define BUF2 (BL_OFF + 256 * ROWB)
#define PSMEM (2 * BUF2)
#define NCHUNK 16
#define TSTR 132

__global__ __launch_bounds__(256, 1) void proj_mma_kernel(
    const float* __restrict__ bq, const float* __restrict__ bk, const float* __restrict__ bv)
{
    const int z = blockIdx.z;
    const int bm = blockIdx.y * 128;
    if (z != 0) {
        const int bat = bm >> 11;
        if ((bm & 2047) >= g_nv[bat]) return;
    }
    extern __shared__ char smem[];
    const uint32_t sbase = smem_u32(smem);
    const int tid = threadIdx.x;
    const __nv_bfloat16* Xh = g_Xh + (size_t)z * MTOT * Hh;
    const __nv_bfloat16* Xl = g_Xl + (size_t)z * MTOT * Hh;
    const __nv_bfloat16* Wh = g_Wh + (size_t)z * Hh * Hh;
    const __nv_bfloat16* Wl = g_Wl + (size_t)z * Hh * Hh;
    const float* bias = (z == 0) ? bq : (z == 1) ? bk : bv;
    const int bn = blockIdx.x * 256;

    const int wid = tid >> 5, lane = tid & 31;
    const int wm = wid & 1;
    const int wn = wid >> 1;
    const int g = lane >> 2;
    const int tig = lane & 3;

    float d[4][8][4];
#pragma unroll
    for (int mt = 0; mt < 4; mt++)
#pragma unroll
        for (int nt = 0; nt < 8; nt++)
#pragma unroll
            for (int r = 0; r < 4; r++) d[mt][nt][r] = 0.f;

    auto issue_chunk = [&](int c, int buf) {
        const int kc = c * 64;
        const uint32_t base = sbase + buf * BUF2;
#pragma unroll
        for (int i = 0; i < 4; i++) {
            int li = i * 256 + tid;
            int row = li >> 3;
            int s = li & 7;
            const size_t go = (size_t)(bm + row) * Hh + kc + s * 8;
            CP_ASYNC16(base + AH_OFF + row * ROWB + s * 16, Xh + go);
            CP_ASYNC16(base + AL_OFF + row * ROWB + s * 16, Xl + go);
        }
#pragma unroll
        for (int i = 0; i < 8; i++) {
            int li = i * 256 + tid;
            int row = li >> 3;
            int s = li & 7;
            const size_t go = (size_t)(bn + row) * Hh + kc + s * 8;
            CP_ASYNC16(base + BH_OFF + row * ROWB + s * 16, Wh + go);
            CP_ASYNC16(base + BL_OFF + row * ROWB + s * 16, Wl + go);
        }
        CP_COMMIT();
    };

    issue_chunk(0, 0);

    for (int c = 0; c < NCHUNK; c++) {
        const int buf = c & 1;
        if (c + 1 < NCHUNK) {
            issue_chunk(c + 1, buf ^ 1);
            CP_WAIT1();
        } else {
            CP_WAIT0();
        }
        __syncthreads();

        const char* base = smem + buf * BUF2;
        const char* AH = base + AH_OFF;
        const char* AL = base + AL_OFF;
        const char* BH = base + BH_OFF;
        const char* BL = base + BL_OFF;
#pragma unroll
        for (int ks = 0; ks < 4; ks++) {
            const int kb = (ks * 16 + 2 * tig) * 2;
            uint32_t afh[4][4], bfh[8][2];
#pragma unroll
            for (int mt = 0; mt < 4; mt++) {
                const char* p = AH + (wm * 64 + mt * 16 + g) * ROWB + kb;
                afh[mt][0] = *(const uint32_t*)(p);
                afh[mt][1] = *(const uint32_t*)(p + 8 * ROWB);
                afh[mt][2] = *(const uint32_t*)(p + 16);
                afh[mt][3] = *(const uint32_t*)(p + 8 * ROWB + 16);
            }
#pragma unroll
            for (int nt = 0; nt < 8; nt++) {
                const char* p = BH + (wn * 64 + nt * 8 + g) * ROWB + kb;
                bfh[nt][0] = *(const uint32_t*)(p);
                bfh[nt][1] = *(const uint32_t*)(p + 16);
            }
#pragma unroll
            for (int mt = 0; mt < 4; mt++)
#pragma unroll
                for (int nt = 0; nt < 8; nt++)
                    mma16816(d[mt][nt], afh[mt], bfh[nt]);
            {
                uint32_t afl[4][4];
#pragma unroll
                for (int mt = 0; mt < 4; mt++) {
                    const char* p = AL + (wm * 64 + mt * 16 + g) * ROWB + kb;
                    afl[mt][0] = *(const uint32_t*)(p);
                    afl[mt][1] = *(const uint32_t*)(p + 8 * ROWB);
                    afl[mt][2] = *(const uint32_t*)(p + 16);
                    afl[mt][3] = *(const uint32_t*)(p + 8 * ROWB + 16);
                }
#pragma unroll
                for (int mt = 0; mt < 4; mt++)
#pragma unroll
                    for (int nt = 0; nt < 8; nt++)
                        mma16816(d[mt][nt], afl[mt], bfh[nt]);
            }
            {
                uint32_t bfl[8][2];
#pragma unroll
                for (int nt = 0; nt < 8; nt++) {
                    const char* p = BL + (wn * 64 + nt * 8 + g) * ROWB + kb;
                    bfl[nt][0] = *(const uint32_t*)(p);
                    bfl[nt][1] = *(const uint32_t*)(p + 16);
                }
#pragma unroll
                for (int mt = 0; mt < 4; mt++)
#pragma unroll
                    for (int nt = 0; nt < 8; nt++)
                        mma16816(d[mt][nt], afh[mt], bfl[nt]);
            }
        }
        __syncthreads();
    }

    if (z == 0) {
        // Q epilogue: bf16 hi/lo, pre-scaled by log2e (attn uses exp2)
#pragma unroll
        for (int nt = 0; nt < 8; nt++) {
            const int col = bn + wn * 64 + nt * 8 + 2 * tig;
            const float2 bb = *(const float2*)&bias[col];
#pragma unroll
            for (int mt = 0; mt < 4; mt++) {
                const int row = bm + wm * 64 + mt * 16 + g;
                float y0 = (d[mt][nt][0] + bb.x) * LOG2E;
                float y1 = (d[mt][nt][1] + bb.y) * LOG2E;
                float y2 = (d[mt][nt][2] + bb.x) * LOG2E;
                float y3 = (d[mt][nt][3] + bb.y) * LOG2E;
                const size_t o0 = ((size_t)row * Hh + col) >> 1;
                const size_t o1 = ((size_t)(row + 8) * Hh + col) >> 1;
                ((uint32_t*)g_Qbh)[o0] = packbf(y0, y1);
                ((uint32_t*)g_Qbh)[o1] = packbf(y2, y3);
                ((uint32_t*)g_Qbl)[o0] = packbf(residbf(y0), residbf(y1));
                ((uint32_t*)g_Qbl)[o1] = packbf(residbf(y2), residbf(y3));
            }
        }
    } else if (z == 1) {
        // K epilogue: permuted fragment units
#pragma unroll
        for (int nt = 0; nt < 8; nt++) {
            const int col = bn + wn * 64 + nt * 8 + 2 * tig;
            const float2 bb = *(const float2*)&bias[col];
            const int head = col >> 6;
            const int dd = col & 63;
            const int kc = dd >> 4;
            const int j = dd & 15;
            const int whi = (j >= 8) ? 1 : 0;
            const int tigk = (j & 7) >> 1;
            const int wunit = head * 64 + (kc * 4 + tigk) * 4 + whi;
#pragma unroll
            for (int mt = 0; mt < 4; mt++) {
                const int row = bm + wm * 64 + mt * 16 + g;
                float y0 = d[mt][nt][0] + bb.x;
                float y1 = d[mt][nt][1] + bb.y;
                float y2 = d[mt][nt][2] + bb.x;
                float y3 = d[mt][nt][3] + bb.y;
                const size_t w0 = (size_t)row * 1024 + wunit;
                const size_t w1 = (size_t)(row + 8) * 1024 + wunit;
                g_Kp[w0] = packbf(y0, y1);
                g_Kp[w0 + 2] = packbf(residbf(y0), residbf(y1));
                g_Kp[w1] = packbf(y2, y3);
                g_Kp[w1 + 2] = packbf(residbf(y2), residbf(y3));
            }
        }
    } else {
        // V epilogue: transpose in smem then write permuted units
        float* smt = (float*)smem;
#pragma unroll
        for (int nt = 0; nt < 8; nt++) {
            const int col = wn * 64 + nt * 8 + 2 * tig;
            const float2 bb = *(const float2*)&bias[bn + col];
#pragma unroll
            for (int mt = 0; mt < 4; mt++) {
                const int row = wm * 64 + mt * 16 + g;
                smt[col * TSTR + row]           = d[mt][nt][0] + bb.x;
                smt[(col + 1) * TSTR + row]     = d[mt][nt][1] + bb.y;
                smt[col * TSTR + row + 8]       = d[mt][nt][2] + bb.x;
                smt[(col + 1) * TSTR + row + 8] = d[mt][nt][3] + bb.y;
            }
        }
        __syncthreads();
        const int b = bm >> 11;
        const int kvb = bm & 2047;
#pragma unroll
        for (int it = 0; it < 16; it++) {
            const int idx = it * 256 + tid;
            const int col = idx >> 4;
            const int seg = idx & 15;
            const int dcol = bn + col;
            const int head = dcol >> 6;
            const int dd = dcol & 63;
            const int bh = b * NHEAD + head;
            const int t = ((kvb + seg * 8) >> 6);
            const int s = seg & 7;
            const int kc = s >> 1;
            const int wb = s & 1;
            const size_t base =
                ((size_t)(bh * HDIM + dd) * (Ss >> 6) + t) * 64 + kc * 16 + wb;
            float v[8];
#pragma unroll
            for (int j = 0; j < 8; j++) v[j] = smt[col * TSTR + seg * 8 + j];
#pragma unroll
            for (int p = 0; p < 4; p++) {
                g_Vp[base + p * 4]     = packbf(v[2*p], v[2*p+1]);
                g_Vp[base + p * 4 + 2] = packbf(residbf(v[2*p]), residbf(v[2*p+1]));
            }
        }
    }
}

// ---------------------------------------------------------------------------
// Tensorized flash attention — 64-row Q tiles, 128 threads, 2 CTAs/SM.
// Permuted K/V (one LDS.128 per fragment group); exp2 softmax (Q pre-scaled).
// ---------------------------------------------------------------------------
#define AROW 144
#define QROWS 64
#define Q_BYTES (QROWS * AROW)
#define KVROW 320
#define KBYTES (64 * KVROW)
#define TILE2 (2 * KBYTES)
#define SM_KV0 (2 * Q_BYTES)
#define ATT2_SMEM (SM_KV0 + 2 * TILE2)

__global__ __launch_bounds__(128, 2) void attn_mma_kernel(float* __restrict__ out)
{
    extern __shared__ char smem[];
    const uint32_t sbase = smem_u32(smem);
    const int tid = threadIdx.x;
    const int q0 = blockIdx.x * QROWS;
    const int h = blockIdx.y;
    const int b = blockIdx.z;
    const int bh = b * NHEAD + h;
    const int nvb = g_nv[b];
    const int ntile = (nvb + 63) >> 6;

    const int wid = tid >> 5, lane = tid & 31;
    const int wq = wid * 16;
    const int g = lane >> 2;
    const int tig = lane & 3;

    {
#pragma unroll
        for (int i = 0; i < 8; i++) {
            int idx = i * 128 + tid;
            int arr = idx >> 9;
            int r = (idx >> 3) & 63;
            int seg = idx & 7;
            const __nv_bfloat16* src =
                (arr ? g_Qbl : g_Qbh) + (size_t)(b * Ss + q0 + r) * Hh + h * HDIM + seg * 8;
            CP_ASYNC16(sbase + arr * Q_BYTES + r * AROW + seg * 16, src);
        }
    }
    auto issue_tile = [&](int t, int buf) {
        const int kv0 = t * 64;
        const uint32_t tb = sbase + SM_KV0 + buf * TILE2;
#pragma unroll
        for (int i = 0; i < 16; i++) {
            int idx = i * 128 + tid;
            int arr = idx >> 10;
            int r = (idx >> 4) & 63;
            int u = idx & 15;
            const uint32_t* src;
            if (arr == 0)
                src = g_Kp + (size_t)(b * Ss + kv0 + r) * 1024 + h * 64 + u * 4;
            else
                src = g_Vp + ((size_t)(bh * HDIM + r) * (Ss >> 6) + t) * 64 + u * 4;
            CP_ASYNC16(tb + arr * KBYTES + r * KVROW + u * 16, src);
        }
    };

    issue_tile(0, 0);
    CP_COMMIT();

    uint32_t aQh[4][4], aQl[4][4];
    float o[8][4];
    float rs0 = 0.f, rs1 = 0.f;
#pragma unroll
    for (int nd = 0; nd < 8; nd++)
#pragma unroll
        for (int r = 0; r < 4; r++) o[nd][r] = 0.f;

    for (int t = 0; t < ntile; t++) {
        const int buf = t & 1;
        if (t + 1 < ntile) {
            issue_tile(t + 1, buf ^ 1);
            CP_COMMIT();
            CP_WAIT1();
        } else {
            CP_WAIT0();
        }
        __syncthreads();

        if (t == 0) {
#pragma unroll
            for (int kc = 0; kc < 4; kc++) {
                const char* p = smem + (wq + g) * AROW + kc * 32 + tig * 4;
                aQh[kc][0] = *(const uint32_t*)(p);
                aQh[kc][1] = *(const uint32_t*)(p + 8 * AROW);
                aQh[kc][2] = *(const uint32_t*)(p + 16);
                aQh[kc][3] = *(const uint32_t*)(p + 8 * AROW + 16);
                const char* q = p + Q_BYTES;
                aQl[kc][0] = *(const uint32_t*)(q);
                aQl[kc][1] = *(const uint32_t*)(q + 8 * AROW);
                aQl[kc][2] = *(const uint32_t*)(q + 16);
                aQl[kc][3] = *(const uint32_t*)(q + 8 * AROW + 16);
            }
        }

        const char* KB = smem + SM_KV0 + buf * TILE2;
        const char* VB = KB + KBYTES;

        float s[8][4];
#pragma unroll
        for (int nt = 0; nt < 8; nt++)
#pragma unroll
            for (int r = 0; r < 4; r++) s[nt][r] = 0.f;

#pragma unroll
        for (int kc = 0; kc < 4; kc++) {
            uint4 kk[8];
#pragma unroll
            for (int nt = 0; nt < 8; nt++)
                kk[nt] = *(const uint4*)(KB + (nt * 8 + g) * KVROW + kc * 64 + tig * 16);
#pragma unroll
            for (int nt = 0; nt < 8; nt++) mma16816b(s[nt], aQh[kc], kk[nt].x, kk[nt].y);
#pragma unroll
            for (int nt = 0; nt < 8; nt++) mma16816b(s[nt], aQl[kc], kk[nt].x, kk[nt].y);
#pragma unroll
            for (int nt = 0; nt < 8; nt++) mma16816b(s[nt], aQh[kc], kk[nt].z, kk[nt].w);
        }

        const int kvb = t * 64 + 2 * tig;
#pragma unroll
        for (int nt = 0; nt < 8; nt++) {
            const int c0 = kvb + nt * 8;
            float p0 = (c0 < nvb) ? exp2f(s[nt][0]) : 0.f;
            float p1 = (c0 + 1 < nvb) ? exp2f(s[nt][1]) : 0.f;
            float p2 = (c0 < nvb) ? exp2f(s[nt][2]) : 0.f;
            float p3 = (c0 + 1 < nvb) ? exp2f(s[nt][3]) : 0.f;
            rs0 += p0 + p1;
            rs1 += p2 + p3;
            s[nt][0] = p0; s[nt][1] = p1; s[nt][2] = p2; s[nt][3] = p3;
        }

        uint32_t pah[4][4], pal[4][4];
#pragma unroll
        for (int kc = 0; kc < 4; kc++) {
            const int n0 = 2 * kc, n1 = 2 * kc + 1;
            pah[kc][0] = prmt7632(s[n0][0], s[n0][1]);
            pah[kc][1] = prmt7632(s[n0][2], s[n0][3]);
            pah[kc][2] = prmt7632(s[n1][0], s[n1][1]);
            pah[kc][3] = prmt7632(s[n1][2], s[n1][3]);
            pal[kc][0] = packbf(s[n0][0] - truncbf(s[n0][0]), s[n0][1] - truncbf(s[n0][1]));
            pal[kc][1] = packbf(s[n0][2] - truncbf(s[n0][2]), s[n0][3] - truncbf(s[n0][3]));
            pal[kc][2] = packbf(s[n1][0] - truncbf(s[n1][0]), s[n1][1] - truncbf(s[n1][1]));
            pal[kc][3] = packbf(s[n1][2] - truncbf(s[n1][2]), s[n1][3] - truncbf(s[n1][3]));
        }

#pragma unroll
        for (int kc = 0; kc < 4; kc++) {
            uint4 vv[8];
#pragma unroll
            for (int nd = 0; nd < 8; nd++)
                vv[nd] = *(const uint4*)(VB + (nd * 8 + g) * KVROW + kc * 64 + tig * 16);
#pragma unroll
            for (int nd = 0; nd < 8; nd++) mma16816b(o[nd], pah[kc], vv[nd].x, vv[nd].y);
#pragma unroll
            for (int nd = 0; nd < 8; nd++) mma16816b(o[nd], pal[kc], vv[nd].x, vv[nd].y);
#pragma unroll
            for (int nd = 0; nd < 8; nd++) mma16816b(o[nd], pah[kc], vv[nd].z, vv[nd].w);
        }
        __syncthreads();
    }

    rs0 += __shfl_xor_sync(0xffffffffu, rs0, 1);
    rs0 += __shfl_xor_sync(0xffffffffu, rs0, 2);
    rs1 += __shfl_xor_sync(0xffffffffu, rs1, 1);
    rs1 += __shfl_xor_sync(0xffffffffu, rs1, 2);
    const float inv0 = 1.f / rs0;
    const float inv1 = 1.f / rs1;
    const int qg = q0 + wq + g;
    float* op0 = out + (size_t)(b * Ss + qg) * Hh + h * HDIM;
    float* op1 = out + (size_t)(b * Ss + qg + 8) * Hh + h * HDIM;
#pragma unroll
    for (int nd = 0; nd < 8; nd++) {
        const int col = nd * 8 + 2 * tig;
        float2 v0 = {o[nd][0] * inv0, o[nd][1] * inv0};
        float2 v1 = {o[nd][2] * inv1, o[nd][3] * inv1};
        *(float2*)&op0[col] = v0;
        *(float2*)&op1[col] = v1;
    }
}

// ---------------------------------------------------------------------------
extern "C" void kernel_launch(void* const* d_in, const int* in_sizes, int n_in,
                              void* d_out, int out_size)
{
    const float* query = (const float*)d_in[0];
    const float* key   = (const float*)d_in[1];
    const float* value = (const float*)d_in[2];
    const int*   mask  = (const int*)  d_in[3];
    const float* Wq    = (const float*)d_in[4];
    const float* bq    = (const float*)d_in[5];
    const float* Wk    = (const float*)d_in[6];
    const float* bk    = (const float*)d_in[7];
    const float* Wv    = (const float*)d_in[8];
    const float* bv    = (const float*)d_in[9];
    float* out = (float*)d_out;

    compact_kernel<<<Bb, 1024>>>(mask);

    split_kernel<<<dim3((MTOT * Hh / 4 + 255) / 256, 6), 256>>>(query, key, value, Wq, Wk, Wv);

    cudaFuncSetAttribute(proj_mma_kernel,
                         cudaFuncAttributeMaxDynamicSharedMemorySize, PSMEM);
    proj_mma_kernel<<<dim3(Hh / 256, MTOT / 128, 3), 256, PSMEM>>>(bq, bk, bv);

    cudaFuncSetAttribute(attn_mma_kernel,
                         cudaFuncAttributeMaxDynamicSharedMemorySize, ATT2_SMEM);
    attn_mma_kernel<<<dim3(Ss / QROWS, NHEAD, Bb), 128, ATT2_SMEM>>>(out);
}